// round 10
// baseline (speedup 1.0000x reference)
#include <cuda_runtime.h>
#include <cstdint>

// Problem constants
#define B_DIM 64
#define T_DIM 32
#define J_DIM 128
#define N_DIM 64
#define IN_F  4096
#define OUT_F 256
#define NTILES (B_DIM * T_DIM)   // 2048
#define MAXQ 8                   // max bts per CTA (grid >= 296)

// Transposed, tf32-rounded weight: WT[in_f][out_f]
__device__ float g_WT[IN_F * OUT_F];

__device__ __forceinline__ uint32_t f32_to_tf32(float x) {
    uint32_t r;
    asm("cvt.rna.tf32.f32 %0, %1;" : "=r"(r) : "f"(x));
    return r;
}

__device__ __forceinline__ void cp_async16_el(void* smem_dst, const void* gsrc,
                                              uint64_t pol) {
    uint32_t d = (uint32_t)__cvta_generic_to_shared(smem_dst);
    asm volatile("cp.async.cg.shared.global.L2::cache_hint [%0], [%1], 16, %2;\n"
                 :: "r"(d), "l"(gsrc), "l"(pol));
}
#define CP_COMMIT() asm volatile("cp.async.commit_group;\n" ::: "memory")
#define CP_WAIT0()  asm volatile("cp.async.wait_group 0;\n" ::: "memory")

__device__ __forceinline__ void prefetch_l2(const void* p) {
    asm volatile("prefetch.global.L2 [%0];" :: "l"(p));
}

// ---------------------------------------------------------------------------
// Kernel 1: transpose full_weight (OUT_F, IN_F) -> g_WT (IN_F, OUT_F), tf32-RNA.
// ---------------------------------------------------------------------------
__global__ void transpose_cvt_kernel(const float* __restrict__ Wfull) {
    __shared__ float tile[32][33];
    int tx = threadIdx.x, ty = threadIdx.y;
    int bx = blockIdx.x;  // IN_F / 32
    int by = blockIdx.y;  // OUT_F / 32
    #pragma unroll
    for (int i = 0; i < 32; i += 8)
        tile[ty + i][tx] = Wfull[(size_t)(by * 32 + ty + i) * IN_F + bx * 32 + tx];
    __syncthreads();
    #pragma unroll
    for (int i = 0; i < 32; i += 8) {
        uint32_t v = f32_to_tf32(tile[tx][ty + i]);
        ((uint32_t*)g_WT)[(size_t)(bx * 32 + ty + i) * OUT_F + by * 32 + tx] = v;
    }
}

// ---------------------------------------------------------------------------
// Kernel 2: persistent CTAs, 2 CTAs/SM, 256 thr (8 warps).
// Per CTA per bt: Y[128 x 256] computed as two sequential 128x128 N-halves.
// A-fragments: direct LDG from X (L1/L2 resident, no smem staging).
// W: smem double-buffered, gather issued a full half-tile ahead (no bubble).
// ---------------------------------------------------------------------------
#define WS_LD 136   // Ws [64][136]: B-frag banks 8*qcol+qrow -> conflict-free
#define WS_ELEMS (64 * WS_LD)

__global__ void __launch_bounds__(256, 2)
masklinear_kernel(const float* __restrict__ X,
                  const int* __restrict__ IDX,
                  float* __restrict__ Y) {
    extern __shared__ float smem[];          // 2 x WS_ELEMS
    __shared__ int s_idx[MAXQ * 64];

    const int tid  = threadIdx.x;
    const int lane = tid & 31;
    const int wid  = tid >> 5;               // 0..7

    // Warp layout: 4(m) x 2(n); warp tile 32 x 64
    const int m0   = (wid >> 1) * 32;
    const int n0   = (wid & 1) * 64;         // within the 128-col half
    const int qrow = lane >> 2;              // 0..7
    const int qcol = lane & 3;               // 0..3

    uint64_t pol;
    asm volatile("createpolicy.fractional.L2::evict_last.b64 %0, 1.0;" : "=l"(pol));

    // ---- Preload ALL my bts' gather indices into smem (once) ----
    int nmine = 0;
    for (int bt = blockIdx.x; bt < NTILES; bt += gridDim.x) nmine++;
    for (int e = tid; e < nmine * 64; e += 256) {
        int q = e >> 6, n = e & 63;
        int bt = blockIdx.x + q * gridDim.x;
        int b = bt >> 5, t = bt & 31;
        s_idx[e] = IDX[((size_t)b * 64 + n) * 32 + t];
    }
    __syncthreads();

    // Gather W half-slice (64 rows x 128 cols) for (q, nh) into Ws.
    auto gather_W = [&](int q, int nh, float* Ws) {
        int rl  = lane >> 2;                       // 0..7 row within warp
        int row = wid * 8 + rl;                    // 0..63
        int idx_r = s_idx[q * 64 + row];
        const float4* src = (const float4*)(g_WT + (size_t)idx_r * OUT_F + nh * 128);
        float4* dst = (float4*)(Ws + row * WS_LD);
        int c0 = lane & 3;                         // 4 lanes per row
        #pragma unroll
        for (int i = 0; i < 8; i++)                // 8 x 16B per lane = 512B/row
            cp_async16_el(dst + c0 + i * 4, src + c0 + i * 4, pol);
        CP_COMMIT();
    };

    // Prologue
    int bt = blockIdx.x;
    gather_W(0, 0, smem);
    // prefetch first X tile to L2
    {
        const float* Xb = X + (size_t)bt * (J_DIM * N_DIM);
        for (int i = tid; i < 256; i += 256)  ;   // no-op keep simple
        #pragma unroll
        for (int i = 0; i < 4; i++)
            prefetch_l2(Xb + (tid + i * 256) * 32);
    }

    int s = 0, q = 0;
    for (; bt < NTILES; bt += gridDim.x, q++) {
        const float* Xbt = X + (size_t)bt * (J_DIM * N_DIM);
        const int nbt = bt + gridDim.x;

        #pragma unroll
        for (int nh = 0; nh < 2; nh++) {
            CP_WAIT0();
            __syncthreads();                       // Ws[s] ready for all warps

            float* Ws = smem + s * WS_ELEMS;

            // Issue next W gather into the other stage (a half-tile ahead)
            if (nh == 0) {
                gather_W(q, 1, smem + (s ^ 1) * WS_ELEMS);
                // prefetch next bt's X to L2 during this half's compute
                if (nbt < NTILES) {
                    const float* Xn = X + (size_t)nbt * (J_DIM * N_DIM);
                    #pragma unroll
                    for (int i = 0; i < 4; i++)
                        prefetch_l2(Xn + (tid + i * 256) * 32);
                }
            } else if (nbt < NTILES) {
                gather_W(q + 1, 0, smem + (s ^ 1) * WS_ELEMS);
            }

            // ---- Compute: warp tile 32 x 64, K = 64 in 8 steps of k8 ----
            float c[2][8][4];
            #pragma unroll
            for (int mt = 0; mt < 2; mt++)
                #pragma unroll
                for (int nt = 0; nt < 8; nt++)
                    #pragma unroll
                    for (int i = 0; i < 4; i++) c[mt][nt][i] = 0.f;

            #pragma unroll
            for (int kt = 0; kt < 8; kt++) {
                const int k0 = kt * 8;
                uint32_t a[2][4];
                #pragma unroll
                for (int mt = 0; mt < 2; mt++) {
                    const float* Ab = Xbt + (m0 + mt * 16 + qrow) * N_DIM + k0 + qcol;
                    a[mt][0] = f32_to_tf32(__ldg(Ab));
                    a[mt][1] = f32_to_tf32(__ldg(Ab + 8 * N_DIM));
                    a[mt][2] = f32_to_tf32(__ldg(Ab + 4));
                    a[mt][3] = f32_to_tf32(__ldg(Ab + 8 * N_DIM + 4));
                }
                uint32_t bf[8][2];
                #pragma unroll
                for (int nt = 0; nt < 8; nt++) {
                    const uint32_t* Bb =
                        (const uint32_t*)(Ws + (k0 + qcol) * WS_LD + n0 + nt * 8 + qrow);
                    bf[nt][0] = Bb[0];
                    bf[nt][1] = Bb[4 * WS_LD];
                }
                #pragma unroll
                for (int mt = 0; mt < 2; mt++)
                    #pragma unroll
                    for (int nt = 0; nt < 8; nt++) {
                        asm volatile(
                            "mma.sync.aligned.m16n8k8.row.col.f32.tf32.tf32.f32 "
                            "{%0,%1,%2,%3}, {%4,%5,%6,%7}, {%8,%9}, {%0,%1,%2,%3};\n"
                            : "+f"(c[mt][nt][0]), "+f"(c[mt][nt][1]),
                              "+f"(c[mt][nt][2]), "+f"(c[mt][nt][3])
                            : "r"(a[mt][0]), "r"(a[mt][1]), "r"(a[mt][2]), "r"(a[mt][3]),
                              "r"(bf[nt][0]), "r"(bf[nt][1]));
                    }
            }

            // ---- Store Y half (streaming, full 32B sectors via float2) ----
            float* Yb = Y + (size_t)bt * (J_DIM * OUT_F) + nh * 128;
            #pragma unroll
            for (int mt = 0; mt < 2; mt++) {
                #pragma unroll
                for (int nt = 0; nt < 8; nt++) {
                    int row = m0 + mt * 16 + qrow;
                    int col = n0 + nt * 8 + qcol * 2;
                    __stcs((float2*)(Yb + (size_t)row * OUT_F + col),
                           make_float2(c[mt][nt][0], c[mt][nt][1]));
                    __stcs((float2*)(Yb + (size_t)(row + 8) * OUT_F + col),
                           make_float2(c[mt][nt][2], c[mt][nt][3]));
                }
            }

            s ^= 1;
        }
    }
}

// ---------------------------------------------------------------------------
extern "C" void kernel_launch(void* const* d_in, const int* in_sizes, int n_in,
                              void* d_out, int out_size) {
    const float* X     = (const float*)d_in[0];   // (B,T,J,N) f32
    const int*   IDX   = (const int*)d_in[1];     // (B,N,T) int32
    const float* Wfull = (const float*)d_in[2];   // (OUT_F, IN_F) f32
    float*       Y     = (float*)d_out;           // (B,T,J,OUT_F) f32

    int nsm = 148;
    cudaDeviceGetAttribute(&nsm, cudaDevAttrMultiProcessorCount, 0);
    if (nsm < 148) nsm = 148;
    int grid = 2 * nsm;                           // 2 CTAs/SM
    if (grid > NTILES) grid = NTILES;             // (never hit: 296/304 < 2048)

    const size_t smem_bytes = 2 * WS_ELEMS * sizeof(float);  // 69632
    cudaFuncSetAttribute(masklinear_kernel,
                         cudaFuncAttributeMaxDynamicSharedMemorySize,
                         (int)smem_bytes);

    transpose_cvt_kernel<<<dim3(IN_F / 32, OUT_F / 32), dim3(32, 8)>>>(Wfull);
    masklinear_kernel<<<grid, 256, smem_bytes>>>(X, IDX, Y);
}

// round 11
// speedup vs baseline: 1.8049x; 1.8049x over previous
#include <cuda_runtime.h>
#include <cstdint>

// Problem constants
#define B_DIM 64
#define T_DIM 32
#define J_DIM 128
#define N_DIM 64
#define IN_F  4096
#define OUT_F 256
#define NTILES (B_DIM * T_DIM)   // 2048 bt tiles
#define MAXQ 6                   // max bts per CTA (grid = 444 -> <=5)

// Transposed, tf32-rounded weight: WT[in_f][out_f]
__device__ float g_WT[IN_F * OUT_F];

__device__ __forceinline__ uint32_t f32_to_tf32(float x) {
    uint32_t r;
    asm("cvt.rna.tf32.f32 %0, %1;" : "=r"(r) : "f"(x));
    return r;
}

__device__ __forceinline__ void cp_async16(void* smem_dst, const void* gsrc) {
    uint32_t d = (uint32_t)__cvta_generic_to_shared(smem_dst);
    asm volatile("cp.async.cg.shared.global [%0], [%1], 16;\n" :: "r"(d), "l"(gsrc));
}
__device__ __forceinline__ void cp_async16_el(void* smem_dst, const void* gsrc,
                                              uint64_t pol) {
    uint32_t d = (uint32_t)__cvta_generic_to_shared(smem_dst);
    asm volatile("cp.async.cg.shared.global.L2::cache_hint [%0], [%1], 16, %2;\n"
                 :: "r"(d), "l"(gsrc), "l"(pol));
}
#define CP_COMMIT() asm volatile("cp.async.commit_group;\n" ::: "memory")
#define CP_WAIT0()  asm volatile("cp.async.wait_group 0;\n" ::: "memory")

// ---------------------------------------------------------------------------
// Kernel 1: transpose full_weight (OUT_F, IN_F) -> g_WT (IN_F, OUT_F), tf32-RNA.
// ---------------------------------------------------------------------------
__global__ void transpose_cvt_kernel(const float* __restrict__ Wfull) {
    __shared__ float tile[32][33];
    int tx = threadIdx.x, ty = threadIdx.y;
    int bx = blockIdx.x;  // IN_F / 32
    int by = blockIdx.y;  // OUT_F / 32
    #pragma unroll
    for (int i = 0; i < 32; i += 8)
        tile[ty + i][tx] = Wfull[(size_t)(by * 32 + ty + i) * IN_F + bx * 32 + tx];
    __syncthreads();
    #pragma unroll
    for (int i = 0; i < 32; i += 8) {
        uint32_t v = f32_to_tf32(tile[tx][ty + i]);
        ((uint32_t*)g_WT)[(size_t)(bx * 32 + ty + i) * OUT_F + by * 32 + tx] = v;
    }
}

// ---------------------------------------------------------------------------
// Kernel 2: persistent CTAs, 3 CTAs/SM, 256 thr (8 warps, 32x32 warp tiles).
// Per CTA per bt: X loaded to smem once; 4 n-quarter computes (128x64 each)
// with W double-buffered (gather issued a full compute-phase ahead).
// ---------------------------------------------------------------------------
#define XS_LD 68    // Xs [128][68]: A-frag banks 4*qrow+qcol -> conflict-free
#define WS_LD 72    // Ws [64][72]:  B-frag banks 8*qcol+8*nt+qrow -> conflict-free
#define XS_ELEMS (128 * XS_LD)          // 8704 floats = 34816 B
#define WS_ELEMS (64 * WS_LD)           // 4608 floats = 18432 B
#define SMEM_FLOATS (XS_ELEMS + 2 * WS_ELEMS)   // 17920 floats = 71680 B

__global__ void __launch_bounds__(256, 3)
masklinear_kernel(const float* __restrict__ X,
                  const int* __restrict__ IDX,
                  float* __restrict__ Y) {
    extern __shared__ float smem[];
    float* Xs = smem;
    float* Wbuf = smem + XS_ELEMS;            // 2 x WS_ELEMS
    __shared__ int s_idx[MAXQ * 64];

    const int tid  = threadIdx.x;
    const int lane = tid & 31;
    const int wid  = tid >> 5;                // 0..7

    // Warp layout: 4(m) x 2(n); warp tile 32 x 32
    const int m0   = (wid >> 1) * 32;
    const int n0   = (wid & 1) * 32;          // within 64-col quarter
    const int qrow = lane >> 2;               // 0..7
    const int qcol = lane & 3;                // 0..3

    uint64_t pol;
    asm volatile("createpolicy.fractional.L2::evict_last.b64 %0, 1.0;" : "=l"(pol));

    // ---- Preload ALL my bts' gather indices into smem (once) ----
    int nmine = 0;
    for (int bt = blockIdx.x; bt < NTILES; bt += gridDim.x) nmine++;
    for (int e = tid; e < nmine * 64; e += 256) {
        int q = e >> 6, n = e & 63;
        int bt = blockIdx.x + q * gridDim.x;
        int b = bt >> 5, t = bt & 31;
        s_idx[e] = IDX[((size_t)b * 64 + n) * 32 + t];
    }
    __syncthreads();

    // Gather W quarter-slice (64 rows x 64 cols) for (q, nq) into Ws.
    auto gather_W = [&](int q, int nq, float* Ws) {
        int row = wid * 8 + (lane >> 2);           // 0..63 (8 rows per warp)
        int idx_r = s_idx[q * 64 + row];
        const float4* src = (const float4*)(g_WT + (size_t)idx_r * OUT_F + nq * 64);
        float4* dst = (float4*)(Ws + row * WS_LD);
        int c0 = lane & 3;                         // 4 lanes per row, 4 chunks each
        #pragma unroll
        for (int i = 0; i < 4; i++)                // 16 x 16B = 256 B per row
            cp_async16_el(dst + c0 + i * 4, src + c0 + i * 4, pol);
        CP_COMMIT();
    };

    // Load X tile (128 x 64 f32, contiguous) into Xs.
    auto load_X = [&](int bt) {
        const float4* Xg = (const float4*)(X + (size_t)bt * (J_DIM * N_DIM));
        #pragma unroll
        for (int i = 0; i < 8; i++) {
            int e = tid + i * 256;                 // 0..2047 16B chunks
            cp_async16(Xs + (e >> 4) * XS_LD + (e & 15) * 4, Xg + e);
        }
        CP_COMMIT();
    };

    // Prologue: first bt's W quarter 0 + X
    int bt = blockIdx.x;
    if (bt < NTILES) {
        gather_W(0, 0, Wbuf);
        load_X(bt);
    }

    int s = 0, q = 0;
    for (; bt < NTILES; bt += gridDim.x, q++) {
        const int nbt = bt + gridDim.x;

        #pragma unroll
        for (int nq = 0; nq < 4; nq++) {
            CP_WAIT0();
            __syncthreads();                       // Ws[s] (and X at nq=0) ready

            float* Ws = Wbuf + s * WS_ELEMS;

            // Issue next W gather into the other stage
            if (nq < 3)
                gather_W(q, nq + 1, Wbuf + (s ^ 1) * WS_ELEMS);
            else if (nbt < NTILES)
                gather_W(q + 1, 0, Wbuf + (s ^ 1) * WS_ELEMS);

            // ---- Compute: warp tile 32 x 32, K = 64 in 8 steps of k8 ----
            float c[2][4][4];
            #pragma unroll
            for (int mt = 0; mt < 2; mt++)
                #pragma unroll
                for (int nt = 0; nt < 4; nt++)
                    #pragma unroll
                    for (int i = 0; i < 4; i++) c[mt][nt][i] = 0.f;

            #pragma unroll
            for (int kt = 0; kt < 8; kt++) {
                const int k0 = kt * 8;
                uint32_t a[2][4];
                #pragma unroll
                for (int mt = 0; mt < 2; mt++) {
                    const float* Ab = Xs + (m0 + mt * 16 + qrow) * XS_LD + k0 + qcol;
                    a[mt][0] = f32_to_tf32(Ab[0]);
                    a[mt][1] = f32_to_tf32(Ab[8 * XS_LD]);
                    a[mt][2] = f32_to_tf32(Ab[4]);
                    a[mt][3] = f32_to_tf32(Ab[8 * XS_LD + 4]);
                }
                uint32_t bf[4][2];
                #pragma unroll
                for (int nt = 0; nt < 4; nt++) {
                    const uint32_t* Bb =
                        (const uint32_t*)(Ws + (k0 + qcol) * WS_LD + n0 + nt * 8 + qrow);
                    bf[nt][0] = Bb[0];
                    bf[nt][1] = Bb[4 * WS_LD];
                }
                #pragma unroll
                for (int mt = 0; mt < 2; mt++)
                    #pragma unroll
                    for (int nt = 0; nt < 4; nt++) {
                        asm volatile(
                            "mma.sync.aligned.m16n8k8.row.col.f32.tf32.tf32.f32 "
                            "{%0,%1,%2,%3}, {%4,%5,%6,%7}, {%8,%9}, {%0,%1,%2,%3};\n"
                            : "+f"(c[mt][nt][0]), "+f"(c[mt][nt][1]),
                              "+f"(c[mt][nt][2]), "+f"(c[mt][nt][3])
                            : "r"(a[mt][0]), "r"(a[mt][1]), "r"(a[mt][2]), "r"(a[mt][3]),
                              "r"(bf[nt][0]), "r"(bf[nt][1]));
                    }
            }

            // ---- Store Y quarter (streaming, full sectors via float2) ----
            float* Yb = Y + (size_t)bt * (J_DIM * OUT_F) + nq * 64;
            #pragma unroll
            for (int mt = 0; mt < 2; mt++) {
                #pragma unroll
                for (int nt = 0; nt < 4; nt++) {
                    int row = m0 + mt * 16 + qrow;
                    int col = n0 + nt * 8 + qcol * 2;
                    __stcs((float2*)(Yb + (size_t)row * OUT_F + col),
                           make_float2(c[mt][nt][0], c[mt][nt][1]));
                    __stcs((float2*)(Yb + (size_t)(row + 8) * OUT_F + col),
                           make_float2(c[mt][nt][2], c[mt][nt][3]));
                }
            }

            s ^= 1;
        }

        // All warps done reading Xs -> safe to overwrite with next bt's X.
        __syncthreads();
        if (nbt < NTILES) load_X(nbt);
    }
}

// ---------------------------------------------------------------------------
extern "C" void kernel_launch(void* const* d_in, const int* in_sizes, int n_in,
                              void* d_out, int out_size) {
    const float* X     = (const float*)d_in[0];   // (B,T,J,N) f32
    const int*   IDX   = (const int*)d_in[1];     // (B,N,T) int32
    const float* Wfull = (const float*)d_in[2];   // (OUT_F, IN_F) f32
    float*       Y     = (float*)d_out;           // (B,T,J,OUT_F) f32

    int nsm = 148;
    cudaDeviceGetAttribute(&nsm, cudaDevAttrMultiProcessorCount, 0);
    if (nsm < 100) nsm = 148;
    int grid = 3 * nsm;                           // 3 CTAs/SM; 444 -> <=5 bts/CTA

    const size_t smem_bytes = SMEM_FLOATS * sizeof(float);  // 71680
    cudaFuncSetAttribute(masklinear_kernel,
                         cudaFuncAttributeMaxDynamicSharedMemorySize,
                         (int)smem_bytes);

    transpose_cvt_kernel<<<dim3(IN_F / 32, OUT_F / 32), dim3(32, 8)>>>(Wfull);
    masklinear_kernel<<<grid, 256, smem_bytes>>>(X, IDX, Y);
}